// round 6
// baseline (speedup 1.0000x reference)
#include <cuda_runtime.h>

#define D 12
#define KMAX 512
#define THREADS 128
#define CAP_TOK 256            // max tokens a block can handle (128 thr x 2)
#define NSM 148

typedef unsigned long long u64;

__device__ float        g_partial[1024];
__device__ unsigned int g_ctr = 0;

__device__ __forceinline__ u64 pack2(float a, float b) {
    u64 r; asm("mov.b64 %0, {%1, %2};" : "=l"(r) : "f"(a), "f"(b)); return r;
}
__device__ __forceinline__ void unpack2(u64 v, float &a, float &b) {
    asm("mov.b64 {%0, %1}, %2;" : "=f"(a), "=f"(b) : "l"(v));
}
__device__ __forceinline__ u64 fma2(u64 a, u64 b, u64 c) {
    u64 r; asm("fma.rn.f32x2 %0, %1, %2, %3;" : "=l"(r) : "l"(a), "l"(b), "l"(c)); return r;
}
__device__ __forceinline__ u64 mul2(u64 a, u64 b) {
    u64 r; asm("mul.rn.f32x2 %0, %1, %2;" : "=l"(r) : "l"(a), "l"(b)); return r;
}
__device__ __forceinline__ u64 add2(u64 a, u64 b) {
    u64 r; asm("add.rn.f32x2 %0, %1, %2;" : "=l"(r) : "l"(a), "l"(b)); return r;
}

// Load one code-pair (codes 2j, 2j+1): 12 packed u64 + packed w2.
__device__ __forceinline__ void load_pair(const u64* __restrict__ s_cb_base,
                                          const u64* __restrict__ s_w2,
                                          int j, u64 c[D], u64 &w2)
{
    const ulonglong2* r = (const ulonglong2*)(s_cb_base + (size_t)j * D);
    #pragma unroll
    for (int h = 0; h < 6; h++) {
        const ulonglong2 v = r[h];
        c[2*h] = v.x; c[2*h+1] = v.y;
    }
    w2 = s_w2[j];
}

__global__ void __launch_bounds__(THREADS, 4)
vq_kernel(const float* __restrict__ x, const float* __restrict__ cb,
          int tokens, int K,
          float* __restrict__ q_out, float* __restrict__ idx_out,
          float* __restrict__ loss_out)
{
    // Code-pair packed codebook: s_cb[j][d] = {cb[2j][d], cb[2j+1][d]}
    __shared__ __align__(16) u64 s_cb[KMAX / 2][D];   // 24576 B
    __shared__ __align__(16) u64 s_w2[KMAX / 2];      // {w2[2j], w2[2j+1]}
    __shared__ float s_red[THREADS];
    __shared__ int   s_last;

    const int tid = threadIdx.x;
    const int K2 = K >> 1;

    // ---- Balanced token partition: all blocks co-resident, equal work ----
    const int start = (int)(((long long)blockIdx.x       * tokens) / gridDim.x);
    const int end   = (int)(((long long)(blockIdx.x + 1) * tokens) / gridDim.x);
    const int t0 = start + tid;
    const int t1 = start + tid + THREADS;
    const bool v0ok = (t0 < end), v1ok = (t1 < end);

    float xv0[D], xv1[D];
    {
        float4 a = {0,0,0,0}, b = {0,0,0,0}, c = {0,0,0,0};
        if (v0ok) { const float4* p = (const float4*)(x + (size_t)t0 * D); a=p[0]; b=p[1]; c=p[2]; }
        xv0[0]=a.x; xv0[1]=a.y; xv0[2]=a.z; xv0[3]=a.w;
        xv0[4]=b.x; xv0[5]=b.y; xv0[6]=b.z; xv0[7]=b.w;
        xv0[8]=c.x; xv0[9]=c.y; xv0[10]=c.z; xv0[11]=c.w;
    }
    {
        float4 a = {0,0,0,0}, b = {0,0,0,0}, c = {0,0,0,0};
        if (v1ok) { const float4* p = (const float4*)(x + (size_t)t1 * D); a=p[0]; b=p[1]; c=p[2]; }
        xv1[0]=a.x; xv1[1]=a.y; xv1[2]=a.z; xv1[3]=a.w;
        xv1[4]=b.x; xv1[5]=b.y; xv1[6]=b.z; xv1[7]=b.w;
        xv1[8]=c.x; xv1[9]=c.y; xv1[10]=c.z; xv1[11]=c.w;
    }

    // ---- Stage codebook code-pair packed ----
    {
        float* s_cb_f = (float*)&s_cb[0][0];
        for (int i = tid; i < K * D; i += THREADS) {
            const int k = i / D, d = i - k * D;
            s_cb_f[(k >> 1) * (2 * D) + d * 2 + (k & 1)] = cb[i];
        }
    }
    __syncthreads();
    // w2 per code: sequential fp32 fma chain (bit-faithful to reference)
    {
        float* s_w2_f = (float*)s_w2;
        const float* s_cb_f = (const float*)&s_cb[0][0];
        for (int k = tid; k < K; k += THREADS) {
            const int j = k >> 1, lane = k & 1;
            float s = 0.f;
            #pragma unroll
            for (int d = 0; d < D; d++) {
                const float w = s_cb_f[j * (2 * D) + d * 2 + lane];
                s = fmaf(w, w, s);
            }
            s_w2_f[j * 2 + lane] = s;
        }
    }
    __syncthreads();

    // ---- x2 (sequential chain), broadcast-pair registers ----
    float x2s0 = 0.f, x2s1 = 0.f;
    #pragma unroll
    for (int d = 0; d < D; d++) x2s0 = fmaf(xv0[d], xv0[d], x2s0);
    #pragma unroll
    for (int d = 0; d < D; d++) x2s1 = fmaf(xv1[d], xv1[d], x2s1);

    u64 xb0[D], xb1[D];
    #pragma unroll
    for (int d = 0; d < D; d++) { xb0[d] = pack2(xv0[d], xv0[d]); xb1[d] = pack2(xv1[d], xv1[d]); }
    const u64 x2b0 = pack2(x2s0, x2s0);
    const u64 x2b1 = pack2(x2s1, x2s1);
    const u64 NEG2 = pack2(-2.0f, -2.0f);

    float best0 = 3.4e38f, best1 = 3.4e38f;
    int   bi0 = 0, bi1 = 0;

    const u64* s_cb_base = &s_cb[0][0];

    // ---- Main loop: ping-pong software pipeline, 2 pairs (4 codes) per iter ----
    u64 cA[D], w2A, cB[D], w2B;
    load_pair(s_cb_base, s_w2, 0, cA, w2A);

    #pragma unroll 1
    for (int j = 0; j < K2; j += 2) {
        // Prefetch pair j+1 while computing pair j
        load_pair(s_cb_base, s_w2, j + 1, cB, w2B);

        // --- compute pair j (codes 2j, 2j+1) ---
        {
            u64 p0 = mul2(xb0[0], cA[0]);
            u64 p1 = mul2(xb1[0], cA[0]);
            #pragma unroll
            for (int d = 1; d < D; d++) {
                p0 = fma2(xb0[d], cA[d], p0);
                p1 = fma2(xb1[d], cA[d], p1);
            }
            const u64 r0 = add2(fma2(p0, NEG2, x2b0), w2A);
            const u64 r1 = add2(fma2(p1, NEG2, x2b1), w2A);
            const int kb = 2 * j;
            float e0, e1;
            unpack2(r0, e0, e1);
            {
                const float m = fminf(e0, e1);
                const int  ci = (e1 < e0) ? (kb + 1) : kb;
                bi0   = (m < best0) ? ci : bi0;
                best0 = fminf(best0, m);
            }
            unpack2(r1, e0, e1);
            {
                const float m = fminf(e0, e1);
                const int  ci = (e1 < e0) ? (kb + 1) : kb;
                bi1   = (m < best1) ? ci : bi1;
                best1 = fminf(best1, m);
            }
        }

        // Prefetch pair j+2 (clamped on last iter) into A while computing B
        const int jn = (j + 2 < K2) ? (j + 2) : (K2 - 1);
        load_pair(s_cb_base, s_w2, jn, cA, w2A);

        // --- compute pair j+1 (codes 2j+2, 2j+3) ---
        {
            u64 p0 = mul2(xb0[0], cB[0]);
            u64 p1 = mul2(xb1[0], cB[0]);
            #pragma unroll
            for (int d = 1; d < D; d++) {
                p0 = fma2(xb0[d], cB[d], p0);
                p1 = fma2(xb1[d], cB[d], p1);
            }
            const u64 r0 = add2(fma2(p0, NEG2, x2b0), w2B);
            const u64 r1 = add2(fma2(p1, NEG2, x2b1), w2B);
            const int kb = 2 * (j + 1);
            float e0, e1;
            unpack2(r0, e0, e1);
            {
                const float m = fminf(e0, e1);
                const int  ci = (e1 < e0) ? (kb + 1) : kb;
                bi0   = (m < best0) ? ci : bi0;
                best0 = fminf(best0, m);
            }
            unpack2(r1, e0, e1);
            {
                const float m = fminf(e0, e1);
                const int  ci = (e1 < e0) ? (kb + 1) : kb;
                bi1   = (m < best1) ? ci : bi1;
                best1 = fminf(best1, m);
            }
        }
    }

    // ---- Emit qst = fl(x + fl(q - x)), indices, loss partials ----
    const float* s_cb_f = (const float*)&s_cb[0][0];
    float lsum = 0.f;

    if (v0ok) {
        const int j = bi0 >> 1, lane = bi0 & 1;
        float qst[D];
        #pragma unroll
        for (int d = 0; d < D; d++) {
            const float q  = s_cb_f[j * (2 * D) + d * 2 + lane];
            const float d1 = q - xv0[d];
            qst[d] = xv0[d] + d1;
            lsum = fmaf(d1, d1, lsum);
        }
        if (q_out) {
            float4* o = (float4*)(q_out + (size_t)t0 * D);
            o[0] = make_float4(qst[0], qst[1], qst[2],  qst[3]);
            o[1] = make_float4(qst[4], qst[5], qst[6],  qst[7]);
            o[2] = make_float4(qst[8], qst[9], qst[10], qst[11]);
        }
        if (idx_out) idx_out[t0] = (float)bi0;
    }
    if (v1ok) {
        const int j = bi1 >> 1, lane = bi1 & 1;
        float qst[D];
        #pragma unroll
        for (int d = 0; d < D; d++) {
            const float q  = s_cb_f[j * (2 * D) + d * 2 + lane];
            const float d1 = q - xv1[d];
            qst[d] = xv1[d] + d1;
            lsum = fmaf(d1, d1, lsum);
        }
        if (q_out) {
            float4* o = (float4*)(q_out + (size_t)t1 * D);
            o[0] = make_float4(qst[0], qst[1], qst[2],  qst[3]);
            o[1] = make_float4(qst[4], qst[5], qst[6],  qst[7]);
            o[2] = make_float4(qst[8], qst[9], qst[10], qst[11]);
        }
        if (idx_out) idx_out[t1] = (float)bi1;
    }

    // ---- Loss: block reduce + last-block finalize (single kernel) ----
    if (loss_out) {
        s_red[tid] = lsum;
        __syncthreads();
        #pragma unroll
        for (int s = THREADS / 2; s > 0; s >>= 1) {
            if (tid < s) s_red[tid] += s_red[tid + s];
            __syncthreads();
        }
        if (tid == 0) {
            g_partial[blockIdx.x] = s_red[0];
            __threadfence();
            const unsigned old = atomicInc(&g_ctr, gridDim.x - 1);  // self-resets
            s_last = (old == gridDim.x - 1);
        }
        __syncthreads();
        if (s_last) {
            __threadfence();
            float v = 0.f;
            for (int i = tid; i < (int)gridDim.x; i += THREADS) v += g_partial[i];
            s_red[tid] = v;
            __syncthreads();
            #pragma unroll
            for (int s = THREADS / 2; s > 0; s >>= 1) {
                if (tid < s) s_red[tid] += s_red[tid + s];
                __syncthreads();
            }
            if (tid == 0) {
                const float m = s_red[0] / ((float)tokens * 12.0f);
                loss_out[0] = m + 0.25f * m;
            }
        }
    }
}

extern "C" void kernel_launch(void* const* d_in, const int* in_sizes, int n_in,
                              void* d_out, int out_size)
{
    const float* x;
    const float* cb;
    int xs, cs;
    if (in_sizes[0] >= in_sizes[1]) {
        x = (const float*)d_in[0]; cb = (const float*)d_in[1];
        xs = in_sizes[0]; cs = in_sizes[1];
    } else {
        x = (const float*)d_in[1]; cb = (const float*)d_in[0];
        xs = in_sizes[1]; cs = in_sizes[0];
    }
    const int tokens = xs / D;
    int K = cs / D;
    if (K > KMAX) K = KMAX;
    K &= ~3;   // loop processes 4 codes/iter (K=512 here)

    float* out = (float*)d_out;
    const long long QN = (long long)tokens * D;

    float* q_out    = nullptr;
    float* idx_out  = nullptr;
    float* loss_out = nullptr;
    if ((long long)out_size == (long long)tokens) {
        idx_out = out;
    } else {
        q_out = out;
        if ((long long)out_size >= QN + tokens)     idx_out  = out + QN;
        if ((long long)out_size >= QN + tokens + 1) loss_out = out + QN + tokens;
        else if ((long long)out_size == QN + 1)     loss_out = out + QN;
    }

    // Balanced single-wave grid: 4 blocks per SM, all co-resident.
    int need = (tokens + CAP_TOK - 1) / CAP_TOK;
    int grid = 4 * NSM;               // 592
    if (grid < need) grid = need;
    if (grid > 1024) grid = 1024;     // g_partial capacity

    vq_kernel<<<grid, THREADS>>>(x, cb, tokens, K, q_out, idx_out, loss_out);
}